// round 1
// baseline (speedup 1.0000x reference)
#include <cuda_runtime.h>
#include <cuda_bf16.h>

#define NMAX 100000

// Scratch (allocation-free rule: device globals)
__device__ float g_bufT[NMAX * 64];   // per-layer "message" features
__device__ float g_bufA[NMAX * 64];   // 64-feat aggregation accumulator
__device__ float g_bufC[NMAX * 16];   // t2 (16-feat messages)
__device__ float g_bufD[NMAX * 16];   // 16-feat aggregation accumulator
__device__ float g_so[NMAX];          // rsqrt(max(deg_out,1))
__device__ float g_si[NMAX];          // rsqrt(max(deg_in,1))
__device__ int   g_degO[NMAX];
__device__ int   g_degI[NMAX];

static inline int cdiv(int a, int b) { return (a + b - 1) / b; }

// ---------------- degrees ----------------
__global__ void k_zero_deg(int n) {
    int i = blockIdx.x * blockDim.x + threadIdx.x;
    if (i < n) { g_degO[i] = 0; g_degI[i] = 0; }
}

__global__ void k_count(const int* __restrict__ src, const int* __restrict__ dst, int E) {
    int e = blockIdx.x * blockDim.x + threadIdx.x;
    if (e < E) {
        atomicAdd(&g_degO[src[e]], 1);
        atomicAdd(&g_degI[dst[e]], 1);
    }
}

__global__ void k_rsqrt(int n) {
    int i = blockIdx.x * blockDim.x + threadIdx.x;
    if (i < n) {
        g_so[i] = rsqrtf((float)max(g_degO[i], 1));
        g_si[i] = rsqrtf((float)max(g_degI[i], 1));
    }
}

// ---------------- zeroing ----------------
__global__ void k_zeroA(int n4) {   // zero g_bufA, n4 = N*16 float4s
    int i = blockIdx.x * blockDim.x + threadIdx.x;
    if (i < n4) ((float4*)g_bufA)[i] = make_float4(0.f, 0.f, 0.f, 0.f);
}
__global__ void k_zeroD(int n4) {   // zero g_bufD, n4 = N*4 float4s
    int i = blockIdx.x * blockDim.x + threadIdx.x;
    if (i < n4) ((float4*)g_bufD)[i] = make_float4(0.f, 0.f, 0.f, 0.f);
}

// ---------------- GEMM0: t0 = (X @ W0) * so ----------------
// X: [N,128], W0: [128,64] -> g_bufT [N,64].  Block: 64 rows x 64 cols, K chunked by 64.
__global__ __launch_bounds__(256) void k_gemm0(const float* __restrict__ X,
                                               const float* __restrict__ W0, int N) {
    __shared__ float sX[64][68];    // padded to kill 4-way bank conflicts
    __shared__ float sW[64][64];
    int tid = threadIdx.x;
    int row0 = blockIdx.x * 64;
    int ty = tid >> 4, tx = tid & 15;

    float acc[4][4] = {};
    #pragma unroll
    for (int kc = 0; kc < 2; kc++) {
        // load X chunk: 64 rows x 64 cols = 1024 float4
        #pragma unroll
        for (int i = 0; i < 4; i++) {
            int flat = i * 256 + tid;            // coalesced
            int r = flat >> 4, q = flat & 15;
            int gr = row0 + r;
            float4 v = make_float4(0.f, 0.f, 0.f, 0.f);
            if (gr < N) v = *(const float4*)(X + (size_t)gr * 128 + kc * 64 + q * 4);
            *(float4*)&sX[r][q * 4] = v;
        }
        // load W chunk: 64 rows x 64 cols
        #pragma unroll
        for (int i = 0; i < 4; i++) {
            int flat = i * 256 + tid;
            int k = flat >> 4, q = flat & 15;
            float4 v = *(const float4*)(W0 + (size_t)(kc * 64 + k) * 64 + q * 4);
            *(float4*)&sW[k][q * 4] = v;
        }
        __syncthreads();
        #pragma unroll 8
        for (int k = 0; k < 64; k++) {
            float a0 = sX[ty * 4 + 0][k], a1 = sX[ty * 4 + 1][k];
            float a2 = sX[ty * 4 + 2][k], a3 = sX[ty * 4 + 3][k];
            float4 w = *(float4*)&sW[k][tx * 4];
            acc[0][0] += a0 * w.x; acc[0][1] += a0 * w.y; acc[0][2] += a0 * w.z; acc[0][3] += a0 * w.w;
            acc[1][0] += a1 * w.x; acc[1][1] += a1 * w.y; acc[1][2] += a1 * w.z; acc[1][3] += a1 * w.w;
            acc[2][0] += a2 * w.x; acc[2][1] += a2 * w.y; acc[2][2] += a2 * w.z; acc[2][3] += a2 * w.w;
            acc[3][0] += a3 * w.x; acc[3][1] += a3 * w.y; acc[3][2] += a3 * w.z; acc[3][3] += a3 * w.w;
        }
        __syncthreads();
    }
    #pragma unroll
    for (int i = 0; i < 4; i++) {
        int gr = row0 + ty * 4 + i;
        if (gr < N) {
            float s = g_so[gr];
            float4 o = make_float4(acc[i][0] * s, acc[i][1] * s, acc[i][2] * s, acc[i][3] * s);
            *(float4*)(g_bufT + (size_t)gr * 64 + tx * 4) = o;
        }
    }
}

// ---------------- 64-feat edge scatter: g_bufA[dst] += g_bufT[src] ----------------
__global__ __launch_bounds__(256) void k_scatter64(const int* __restrict__ src,
                                                   const int* __restrict__ dst, int E) {
    int idx = blockIdx.x * blockDim.x + threadIdx.x;
    int total = E * 16;
    if (idx >= total) return;
    int e = idx >> 4;
    int c = (idx & 15) << 2;
    int s = __ldg(&src[e]);
    int d = __ldg(&dst[e]);
    float4 v = *(const float4*)(g_bufT + (size_t)s * 64 + c);
    float* p = g_bufA + (size_t)d * 64 + c;
    asm volatile("red.global.add.v4.f32 [%0], {%1,%2,%3,%4};"
                 :: "l"(p), "f"(v.x), "f"(v.y), "f"(v.z), "f"(v.w) : "memory");
}

// ---------------- epilogue L0 / message L1: t1 = relu(agg*si + b0) * so ----------------
__global__ void k_epi1(const float* __restrict__ b0, int N) {
    int idx = blockIdx.x * blockDim.x + threadIdx.x;
    if (idx >= N * 16) return;
    int row = idx >> 4;
    int qc = (idx & 15) * 4;
    float si = g_si[row], so = g_so[row];
    float4 v = *(float4*)(g_bufA + (size_t)row * 64 + qc);
    float4 b = *(const float4*)(b0 + qc);
    float4 o;
    o.x = fmaxf(v.x * si + b.x, 0.f) * so;
    o.y = fmaxf(v.y * si + b.y, 0.f) * so;
    o.z = fmaxf(v.z * si + b.z, 0.f) * so;
    o.w = fmaxf(v.w * si + b.w, 0.f) * so;
    *(float4*)(g_bufT + (size_t)row * 64 + qc) = o;
}

// ---------------- fused L1 GEMM + L2 GEMM ----------------
// in = g_bufA * si; h1 = relu(in @ W1 + b1); t2 = (h1 @ W2) * so -> g_bufC [N,16]
__global__ __launch_bounds__(256) void k_fused12(const float* __restrict__ W1,
                                                 const float* __restrict__ b1,
                                                 const float* __restrict__ W2, int N) {
    __shared__ float sIn[64][68];   // reused as sH after phase 1
    __shared__ float sW1[64][64];
    __shared__ float sW2[64][16];
    int tid = threadIdx.x;
    int row0 = blockIdx.x * 64;
    int ty = tid >> 4, tx = tid & 15;

    // load in-tile (scaled by si), W1, W2
    #pragma unroll
    for (int i = 0; i < 4; i++) {
        int flat = i * 256 + tid;
        int r = flat >> 4, q = flat & 15;
        int gr = row0 + r;
        float4 v = make_float4(0.f, 0.f, 0.f, 0.f);
        if (gr < N) {
            float si = g_si[gr];
            v = *(const float4*)(g_bufA + (size_t)gr * 64 + q * 4);
            v.x *= si; v.y *= si; v.z *= si; v.w *= si;
        }
        *(float4*)&sIn[r][q * 4] = v;
    }
    #pragma unroll
    for (int i = 0; i < 4; i++) {
        int flat = i * 256 + tid;
        int k = flat >> 4, q = flat & 15;
        *(float4*)&sW1[k][q * 4] = *(const float4*)(W1 + (size_t)k * 64 + q * 4);
    }
    {
        int k = tid >> 2, q = tid & 3;   // 64x16 = 256 float4
        *(float4*)&sW2[k][q * 4] = *(const float4*)(W2 + (size_t)k * 16 + q * 4);
    }
    __syncthreads();

    // phase 1: h1 tile
    float acc[4][4] = {};
    #pragma unroll 8
    for (int k = 0; k < 64; k++) {
        float a0 = sIn[ty * 4 + 0][k], a1 = sIn[ty * 4 + 1][k];
        float a2 = sIn[ty * 4 + 2][k], a3 = sIn[ty * 4 + 3][k];
        float4 w = *(float4*)&sW1[k][tx * 4];
        acc[0][0] += a0 * w.x; acc[0][1] += a0 * w.y; acc[0][2] += a0 * w.z; acc[0][3] += a0 * w.w;
        acc[1][0] += a1 * w.x; acc[1][1] += a1 * w.y; acc[1][2] += a1 * w.z; acc[1][3] += a1 * w.w;
        acc[2][0] += a2 * w.x; acc[2][1] += a2 * w.y; acc[2][2] += a2 * w.z; acc[2][3] += a2 * w.w;
        acc[3][0] += a3 * w.x; acc[3][1] += a3 * w.y; acc[3][2] += a3 * w.z; acc[3][3] += a3 * w.w;
    }
    __syncthreads();  // all reads of sIn done
    float4 bb = *(const float4*)(b1 + tx * 4);
    #pragma unroll
    for (int i = 0; i < 4; i++) {
        float4 h;
        h.x = fmaxf(acc[i][0] + bb.x, 0.f);
        h.y = fmaxf(acc[i][1] + bb.y, 0.f);
        h.z = fmaxf(acc[i][2] + bb.z, 0.f);
        h.w = fmaxf(acc[i][3] + bb.w, 0.f);
        *(float4*)&sIn[ty * 4 + i][tx * 4] = h;   // sIn now holds h1
    }
    __syncthreads();

    // phase 2: t2 = (h1 @ W2) * so, 64x16 output, 4 elems/thread
    int row = tid >> 2;
    int cb = (tid & 3) * 4;
    float4 o = make_float4(0.f, 0.f, 0.f, 0.f);
    #pragma unroll 8
    for (int k = 0; k < 64; k++) {
        float a = sIn[row][k];
        float4 w = *(float4*)&sW2[k][cb];
        o.x += a * w.x; o.y += a * w.y; o.z += a * w.z; o.w += a * w.w;
    }
    int gr = row0 + row;
    if (gr < N) {
        float s = g_so[gr];
        o.x *= s; o.y *= s; o.z *= s; o.w *= s;
        *(float4*)(g_bufC + (size_t)gr * 16 + cb) = o;
    }
}

// ---------------- 16-feat edge scatter: g_bufD[dst] += g_bufC[src] ----------------
__global__ __launch_bounds__(256) void k_scatter16(const int* __restrict__ src,
                                                   const int* __restrict__ dst, int E) {
    int idx = blockIdx.x * blockDim.x + threadIdx.x;
    int total = E * 4;
    if (idx >= total) return;
    int e = idx >> 2;
    int c = (idx & 3) << 2;
    int s = __ldg(&src[e]);
    int d = __ldg(&dst[e]);
    float4 v = *(const float4*)(g_bufC + (size_t)s * 16 + c);
    float* p = g_bufD + (size_t)d * 16 + c;
    asm volatile("red.global.add.v4.f32 [%0], {%1,%2,%3,%4};"
                 :: "l"(p), "f"(v.x), "f"(v.y), "f"(v.z), "f"(v.w) : "memory");
}

// ---------------- final: out = agg2 * si + b2 ----------------
__global__ void k_final(const float* __restrict__ b2, float* __restrict__ out, int N) {
    int idx = blockIdx.x * blockDim.x + threadIdx.x;
    if (idx >= N * 4) return;
    int row = idx >> 2;
    int qc = (idx & 3) * 4;
    float si = g_si[row];
    float4 v = *(float4*)(g_bufD + (size_t)row * 16 + qc);
    float4 b = *(const float4*)(b2 + qc);
    float4 o = make_float4(v.x * si + b.x, v.y * si + b.y, v.z * si + b.z, v.w * si + b.w);
    *(float4*)(out + (size_t)row * 16 + qc) = o;
}

extern "C" void kernel_launch(void* const* d_in, const int* in_sizes, int n_in,
                              void* d_out, int out_size) {
    const float* X   = (const float*)d_in[0];
    const int*   src = (const int*)d_in[1];
    const int*   dst = (const int*)d_in[2];
    const float* W0  = (const float*)d_in[3];
    const float* b0  = (const float*)d_in[4];
    const float* W1  = (const float*)d_in[5];
    const float* b1  = (const float*)d_in[6];
    const float* W2  = (const float*)d_in[7];
    const float* b2  = (const float*)d_in[8];
    float* out = (float*)d_out;

    int N = in_sizes[0] / 128;
    int E = in_sizes[1];

    // degrees + normalization factors
    k_zero_deg<<<cdiv(N, 256), 256>>>(N);
    k_count<<<cdiv(E, 256), 256>>>(src, dst, E);
    k_rsqrt<<<cdiv(N, 256), 256>>>(N);

    // Layer 0
    k_gemm0<<<cdiv(N, 64), 256>>>(X, W0, N);
    k_zeroA<<<cdiv(N * 16, 256), 256>>>(N * 16);
    k_scatter64<<<cdiv(E * 16, 256), 256>>>(src, dst, E);
    k_epi1<<<cdiv(N * 16, 256), 256>>>(b0, N);

    // Layer 1 aggregation (messages already in g_bufT)
    k_zeroA<<<cdiv(N * 16, 256), 256>>>(N * 16);
    k_scatter64<<<cdiv(E * 16, 256), 256>>>(src, dst, E);

    // Layer 1 GEMM fused with Layer 2 GEMM
    k_fused12<<<cdiv(N, 64), 256>>>(W1, b1, W2, N);

    // Layer 2 aggregation + final
    k_zeroD<<<cdiv(N * 4, 256), 256>>>(N * 4);
    k_scatter16<<<cdiv(E * 4, 256), 256>>>(src, dst, E);
    k_final<<<cdiv(N * 4, 256), 256>>>(b2, out, N);
}

// round 2
// speedup vs baseline: 1.4711x; 1.4711x over previous
#include <cuda_runtime.h>
#include <cuda_bf16.h>

#define NMAX 100000
#define EMAX 1600000

// Scratch (allocation-free rule: device globals)
__device__ float g_bufT[NMAX * 64];   // message features
__device__ float g_bufA[NMAX * 64];   // second message buffer
__device__ float g_bufC[NMAX * 16];   // t2 (16-feat messages)
__device__ float g_so[NMAX];          // rsqrt(max(deg_out,1))
__device__ float g_si[NMAX];          // rsqrt(max(deg_in,1))
__device__ int   g_degO[NMAX];
__device__ int   g_degI[NMAX];
__device__ int   g_cursor[NMAX];
__device__ int   g_rowptr[NMAX];      // exclusive prefix sum of degI
__device__ int   g_csrc[EMAX];        // CSR: src ids grouped by dst
__device__ int   g_bsums[512];        // scan block sums

static inline int cdiv(int a, int b) { return (a + b - 1) / b; }

// ---------------- degrees ----------------
__global__ void k_zero_deg(int n) {
    int i = blockIdx.x * blockDim.x + threadIdx.x;
    if (i < n) { g_degO[i] = 0; g_degI[i] = 0; g_cursor[i] = 0; }
}

__global__ void k_count(const int* __restrict__ src, const int* __restrict__ dst, int E) {
    int e = blockIdx.x * blockDim.x + threadIdx.x;
    if (e < E) {
        atomicAdd(&g_degO[src[e]], 1);
        atomicAdd(&g_degI[dst[e]], 1);
    }
}

__global__ void k_rsqrt(int n) {
    int i = blockIdx.x * blockDim.x + threadIdx.x;
    if (i < n) {
        g_so[i] = rsqrtf((float)max(g_degO[i], 1));
        g_si[i] = rsqrtf((float)max(g_degI[i], 1));
    }
}

// ---------------- exclusive scan of g_degI -> g_rowptr ----------------
__global__ void k_scan1(int n) {
    __shared__ int sh[512];
    int tid = threadIdx.x;
    int i = blockIdx.x * 512 + tid;
    int v = (i < n) ? g_degI[i] : 0;
    sh[tid] = v;
    __syncthreads();
    #pragma unroll
    for (int off = 1; off < 512; off <<= 1) {
        int t = (tid >= off) ? sh[tid - off] : 0;
        __syncthreads();
        sh[tid] += t;
        __syncthreads();
    }
    if (i < n) g_rowptr[i] = sh[tid] - v;
    if (tid == 511) g_bsums[blockIdx.x] = sh[511];
}

__global__ void k_scan2(int nb) {
    __shared__ int sh[256];
    int tid = threadIdx.x;
    int v = (tid < nb) ? g_bsums[tid] : 0;
    sh[tid] = v;
    __syncthreads();
    #pragma unroll
    for (int off = 1; off < 256; off <<= 1) {
        int t = (tid >= off) ? sh[tid - off] : 0;
        __syncthreads();
        sh[tid] += t;
        __syncthreads();
    }
    if (tid < nb) g_bsums[tid] = sh[tid] - v;
}

__global__ void k_scan3(int n) {
    int i = blockIdx.x * 512 + threadIdx.x;
    if (i < n) g_rowptr[i] += g_bsums[blockIdx.x];
}

__global__ void k_fill(const int* __restrict__ src, const int* __restrict__ dst, int E) {
    int e = blockIdx.x * blockDim.x + threadIdx.x;
    if (e < E) {
        int d = dst[e];
        int pos = g_rowptr[d] + atomicAdd(&g_cursor[d], 1);
        g_csrc[pos] = src[e];
    }
}

// ---------------- GEMM0: g_bufT = (X @ W0) * so ----------------
// 128x64 block tile, 8x4 register tile, k vectorized by 4.
__global__ __launch_bounds__(256) void k_gemm0(const float* __restrict__ X,
                                               const float* __restrict__ W0, int N) {
    __shared__ float sX[128][68];
    __shared__ float sW[64][64];
    int tid = threadIdx.x;
    int row0 = blockIdx.x * 128;
    int ty = tid >> 4;   // 0..15 : rows ty*8..+7
    int tx = tid & 15;   // cols tx*4..+3

    float acc[8][4] = {};
    #pragma unroll
    for (int kc = 0; kc < 2; kc++) {
        #pragma unroll
        for (int i = 0; i < 8; i++) {
            int flat = i * 256 + tid;
            int r = flat >> 4, q = flat & 15;
            int gr = row0 + r;
            float4 v = make_float4(0.f, 0.f, 0.f, 0.f);
            if (gr < N) v = *(const float4*)(X + (size_t)gr * 128 + kc * 64 + q * 4);
            *(float4*)&sX[r][q * 4] = v;
        }
        #pragma unroll
        for (int i = 0; i < 4; i++) {
            int flat = i * 256 + tid;
            int k = flat >> 4, q = flat & 15;
            *(float4*)&sW[k][q * 4] = *(const float4*)(W0 + (size_t)(kc * 64 + k) * 64 + q * 4);
        }
        __syncthreads();
        #pragma unroll
        for (int k4 = 0; k4 < 16; k4++) {
            float4 w0 = *(float4*)&sW[k4 * 4 + 0][tx * 4];
            float4 w1 = *(float4*)&sW[k4 * 4 + 1][tx * 4];
            float4 w2 = *(float4*)&sW[k4 * 4 + 2][tx * 4];
            float4 w3 = *(float4*)&sW[k4 * 4 + 3][tx * 4];
            #pragma unroll
            for (int i = 0; i < 8; i++) {
                float4 a = *(float4*)&sX[ty * 8 + i][k4 * 4];
                acc[i][0] += a.x * w0.x + a.y * w1.x + a.z * w2.x + a.w * w3.x;
                acc[i][1] += a.x * w0.y + a.y * w1.y + a.z * w2.y + a.w * w3.y;
                acc[i][2] += a.x * w0.z + a.y * w1.z + a.z * w2.z + a.w * w3.z;
                acc[i][3] += a.x * w0.w + a.y * w1.w + a.z * w2.w + a.w * w3.w;
            }
        }
        __syncthreads();
    }
    #pragma unroll
    for (int i = 0; i < 8; i++) {
        int gr = row0 + ty * 8 + i;
        if (gr < N) {
            float s = g_so[gr];
            float4 o = make_float4(acc[i][0] * s, acc[i][1] * s, acc[i][2] * s, acc[i][3] * s);
            *(float4*)(g_bufT + (size_t)gr * 64 + tx * 4) = o;
        }
    }
}

// ---------------- CSR pull, 64 feats, L0 epilogue ----------------
// g_bufA[node] = relu( (sum g_bufT[src]) * si + b0 ) * so
__global__ __launch_bounds__(256) void k_pull64_l0(const float* __restrict__ b0, int N) {
    int node = blockIdx.x * 16 + (threadIdx.x >> 4);
    if (node >= N) return;
    int lane = threadIdx.x & 15;
    int start = g_rowptr[node], cnt = g_degI[node];
    float4 acc = make_float4(0.f, 0.f, 0.f, 0.f);
    int j = 0;
    for (; j + 1 < cnt; j += 2) {
        int s0 = __ldg(&g_csrc[start + j]);
        int s1 = __ldg(&g_csrc[start + j + 1]);
        float4 v0 = *(const float4*)(g_bufT + (size_t)s0 * 64 + lane * 4);
        float4 v1 = *(const float4*)(g_bufT + (size_t)s1 * 64 + lane * 4);
        acc.x += v0.x + v1.x; acc.y += v0.y + v1.y;
        acc.z += v0.z + v1.z; acc.w += v0.w + v1.w;
    }
    if (j < cnt) {
        int s0 = __ldg(&g_csrc[start + j]);
        float4 v0 = *(const float4*)(g_bufT + (size_t)s0 * 64 + lane * 4);
        acc.x += v0.x; acc.y += v0.y; acc.z += v0.z; acc.w += v0.w;
    }
    float si = g_si[node], so = g_so[node];
    float4 b = *(const float4*)(b0 + lane * 4);
    float4 o;
    o.x = fmaxf(acc.x * si + b.x, 0.f) * so;
    o.y = fmaxf(acc.y * si + b.y, 0.f) * so;
    o.z = fmaxf(acc.z * si + b.z, 0.f) * so;
    o.w = fmaxf(acc.w * si + b.w, 0.f) * so;
    *(float4*)(g_bufA + (size_t)node * 64 + lane * 4) = o;
}

// ---------------- CSR pull, 64 feats, L1 aggregation ----------------
// g_bufT[node] = (sum g_bufA[src]) * si     (pre-scaled input to GEMM1)
__global__ __launch_bounds__(256) void k_pull64_l1(int N) {
    int node = blockIdx.x * 16 + (threadIdx.x >> 4);
    if (node >= N) return;
    int lane = threadIdx.x & 15;
    int start = g_rowptr[node], cnt = g_degI[node];
    float4 acc = make_float4(0.f, 0.f, 0.f, 0.f);
    int j = 0;
    for (; j + 1 < cnt; j += 2) {
        int s0 = __ldg(&g_csrc[start + j]);
        int s1 = __ldg(&g_csrc[start + j + 1]);
        float4 v0 = *(const float4*)(g_bufA + (size_t)s0 * 64 + lane * 4);
        float4 v1 = *(const float4*)(g_bufA + (size_t)s1 * 64 + lane * 4);
        acc.x += v0.x + v1.x; acc.y += v0.y + v1.y;
        acc.z += v0.z + v1.z; acc.w += v0.w + v1.w;
    }
    if (j < cnt) {
        int s0 = __ldg(&g_csrc[start + j]);
        float4 v0 = *(const float4*)(g_bufA + (size_t)s0 * 64 + lane * 4);
        acc.x += v0.x; acc.y += v0.y; acc.z += v0.z; acc.w += v0.w;
    }
    float si = g_si[node];
    float4 o = make_float4(acc.x * si, acc.y * si, acc.z * si, acc.w * si);
    *(float4*)(g_bufT + (size_t)node * 64 + lane * 4) = o;
}

// ---------------- fused L1 GEMM + L2 GEMM ----------------
// in = g_bufT (already si-scaled); h1 = relu(in @ W1 + b1); g_bufC = (h1 @ W2) * so
__global__ __launch_bounds__(256) void k_fused12(const float* __restrict__ W1,
                                                 const float* __restrict__ b1,
                                                 const float* __restrict__ W2, int N) {
    __shared__ float sIn[64][68];
    __shared__ float sW1[64][64];
    __shared__ float sW2[64][16];
    int tid = threadIdx.x;
    int row0 = blockIdx.x * 64;
    int ty = tid >> 4, tx = tid & 15;

    #pragma unroll
    for (int i = 0; i < 4; i++) {
        int flat = i * 256 + tid;
        int r = flat >> 4, q = flat & 15;
        int gr = row0 + r;
        float4 v = make_float4(0.f, 0.f, 0.f, 0.f);
        if (gr < N) v = *(const float4*)(g_bufT + (size_t)gr * 64 + q * 4);
        *(float4*)&sIn[r][q * 4] = v;
    }
    #pragma unroll
    for (int i = 0; i < 4; i++) {
        int flat = i * 256 + tid;
        int k = flat >> 4, q = flat & 15;
        *(float4*)&sW1[k][q * 4] = *(const float4*)(W1 + (size_t)k * 64 + q * 4);
    }
    {
        int k = tid >> 2, q = tid & 3;
        *(float4*)&sW2[k][q * 4] = *(const float4*)(W2 + (size_t)k * 16 + q * 4);
    }
    __syncthreads();

    // phase 1: h1 tile (4x4 per thread)
    float acc[4][4] = {};
    #pragma unroll
    for (int k4 = 0; k4 < 16; k4++) {
        float4 w0 = *(float4*)&sW1[k4 * 4 + 0][tx * 4];
        float4 w1 = *(float4*)&sW1[k4 * 4 + 1][tx * 4];
        float4 w2 = *(float4*)&sW1[k4 * 4 + 2][tx * 4];
        float4 w3 = *(float4*)&sW1[k4 * 4 + 3][tx * 4];
        #pragma unroll
        for (int i = 0; i < 4; i++) {
            float4 a = *(float4*)&sIn[ty * 4 + i][k4 * 4];
            acc[i][0] += a.x * w0.x + a.y * w1.x + a.z * w2.x + a.w * w3.x;
            acc[i][1] += a.x * w0.y + a.y * w1.y + a.z * w2.y + a.w * w3.y;
            acc[i][2] += a.x * w0.z + a.y * w1.z + a.z * w2.z + a.w * w3.z;
            acc[i][3] += a.x * w0.w + a.y * w1.w + a.z * w2.w + a.w * w3.w;
        }
    }
    __syncthreads();
    float4 bb = *(const float4*)(b1 + tx * 4);
    #pragma unroll
    for (int i = 0; i < 4; i++) {
        float4 h;
        h.x = fmaxf(acc[i][0] + bb.x, 0.f);
        h.y = fmaxf(acc[i][1] + bb.y, 0.f);
        h.z = fmaxf(acc[i][2] + bb.z, 0.f);
        h.w = fmaxf(acc[i][3] + bb.w, 0.f);
        *(float4*)&sIn[ty * 4 + i][tx * 4] = h;   // sIn now holds h1
    }
    __syncthreads();

    // phase 2: g_bufC = (h1 @ W2) * so   (64x16 per block, 4 elems/thread)
    int row = tid >> 2;
    int cb = (tid & 3) * 4;
    float4 o = make_float4(0.f, 0.f, 0.f, 0.f);
    #pragma unroll 8
    for (int k = 0; k < 64; k++) {
        float a = sIn[row][k];
        float4 w = *(float4*)&sW2[k][cb];
        o.x += a * w.x; o.y += a * w.y; o.z += a * w.z; o.w += a * w.w;
    }
    int gr = row0 + row;
    if (gr < N) {
        float s = g_so[gr];
        o.x *= s; o.y *= s; o.z *= s; o.w *= s;
        *(float4*)(g_bufC + (size_t)gr * 16 + cb) = o;
    }
}

// ---------------- CSR pull, 16 feats, final ----------------
// out[node] = (sum g_bufC[src]) * si + b2
__global__ __launch_bounds__(256) void k_pull16(const float* __restrict__ b2,
                                                float* __restrict__ out, int N) {
    int node = blockIdx.x * 64 + (threadIdx.x >> 2);
    if (node >= N) return;
    int lane = threadIdx.x & 3;
    int start = g_rowptr[node], cnt = g_degI[node];
    float4 acc = make_float4(0.f, 0.f, 0.f, 0.f);
    int j = 0;
    for (; j + 3 < cnt; j += 4) {
        int s0 = __ldg(&g_csrc[start + j]);
        int s1 = __ldg(&g_csrc[start + j + 1]);
        int s2 = __ldg(&g_csrc[start + j + 2]);
        int s3 = __ldg(&g_csrc[start + j + 3]);
        float4 v0 = *(const float4*)(g_bufC + (size_t)s0 * 16 + lane * 4);
        float4 v1 = *(const float4*)(g_bufC + (size_t)s1 * 16 + lane * 4);
        float4 v2 = *(const float4*)(g_bufC + (size_t)s2 * 16 + lane * 4);
        float4 v3 = *(const float4*)(g_bufC + (size_t)s3 * 16 + lane * 4);
        acc.x += (v0.x + v1.x) + (v2.x + v3.x);
        acc.y += (v0.y + v1.y) + (v2.y + v3.y);
        acc.z += (v0.z + v1.z) + (v2.z + v3.z);
        acc.w += (v0.w + v1.w) + (v2.w + v3.w);
    }
    for (; j < cnt; j++) {
        int s0 = __ldg(&g_csrc[start + j]);
        float4 v0 = *(const float4*)(g_bufC + (size_t)s0 * 16 + lane * 4);
        acc.x += v0.x; acc.y += v0.y; acc.z += v0.z; acc.w += v0.w;
    }
    float si = g_si[node];
    float4 b = *(const float4*)(b2 + lane * 4);
    float4 o = make_float4(acc.x * si + b.x, acc.y * si + b.y,
                           acc.z * si + b.z, acc.w * si + b.w);
    *(float4*)(out + (size_t)node * 16 + lane * 4) = o;
}

extern "C" void kernel_launch(void* const* d_in, const int* in_sizes, int n_in,
                              void* d_out, int out_size) {
    const float* X   = (const float*)d_in[0];
    const int*   src = (const int*)d_in[1];
    const int*   dst = (const int*)d_in[2];
    const float* W0  = (const float*)d_in[3];
    const float* b0  = (const float*)d_in[4];
    const float* W1  = (const float*)d_in[5];
    const float* b1  = (const float*)d_in[6];
    const float* W2  = (const float*)d_in[7];
    const float* b2  = (const float*)d_in[8];
    float* out = (float*)d_out;

    int N = in_sizes[0] / 128;
    int E = in_sizes[1];
    int nb = cdiv(N, 512);

    // degrees + norms + CSR
    k_zero_deg<<<cdiv(N, 256), 256>>>(N);
    k_count<<<cdiv(E, 256), 256>>>(src, dst, E);
    k_rsqrt<<<cdiv(N, 256), 256>>>(N);
    k_scan1<<<nb, 512>>>(N);
    k_scan2<<<1, 256>>>(nb);
    k_scan3<<<nb, 512>>>(N);
    k_fill<<<cdiv(E, 256), 256>>>(src, dst, E);

    // Layer 0
    k_gemm0<<<cdiv(N, 128), 256>>>(X, W0, N);
    k_pull64_l0<<<cdiv(N, 16), 256>>>(b0, N);

    // Layer 1 aggregation + fused GEMMs (L1 + L2)
    k_pull64_l1<<<cdiv(N, 16), 256>>>(N);
    k_fused12<<<cdiv(N, 64), 256>>>(W1, b1, W2, N);

    // Layer 2 aggregation + final
    k_pull16<<<cdiv(N, 64), 256>>>(b2, out, N);
}

// round 3
// speedup vs baseline: 1.5130x; 1.0285x over previous
#include <cuda_runtime.h>
#include <cuda_bf16.h>

#define NMAX 100000
#define EMAX 1600000

// Scratch (allocation-free rule: device globals)
__device__ __nv_bfloat16 g_bufT[NMAX * 64];  // bf16 messages (t0, L0)
__device__ __nv_bfloat16 g_bufA[NMAX * 64];  // bf16 messages (h0*so, L1)
__device__ float g_agg[NMAX * 64];           // fp32 aggregated input to fused GEMM
__device__ float g_bufC[NMAX * 16];          // t2 (16-feat messages, fp32)
__device__ float g_so[NMAX];                 // rsqrt(max(deg_out,1))
__device__ float g_si[NMAX];                 // rsqrt(max(deg_in,1))
__device__ int   g_degO[NMAX];
__device__ int   g_degI[NMAX];
__device__ int   g_cursor[NMAX];
__device__ int   g_rowptr[NMAX];             // exclusive prefix sum of degI
__device__ int   g_csrc[EMAX];               // CSR: src ids grouped by dst
__device__ int   g_bsums[512];               // scan block sums

static inline int cdiv(int a, int b) { return (a + b - 1) / b; }

// ---- bf16x4 pack/unpack ----
__device__ __forceinline__ float4 bf4_to_f4(uint2 r) {
    __nv_bfloat162 lo = *reinterpret_cast<__nv_bfloat162*>(&r.x);
    __nv_bfloat162 hi = *reinterpret_cast<__nv_bfloat162*>(&r.y);
    float2 a = __bfloat1622float2(lo), b = __bfloat1622float2(hi);
    return make_float4(a.x, a.y, b.x, b.y);
}
__device__ __forceinline__ uint2 f4_to_bf4(float4 v) {
    __nv_bfloat162 lo = __float22bfloat162_rn(make_float2(v.x, v.y));
    __nv_bfloat162 hi = __float22bfloat162_rn(make_float2(v.z, v.w));
    uint2 r;
    r.x = *reinterpret_cast<unsigned*>(&lo);
    r.y = *reinterpret_cast<unsigned*>(&hi);
    return r;
}

// ---------------- degrees ----------------
__global__ void k_zero_deg(int n) {
    int i = blockIdx.x * blockDim.x + threadIdx.x;
    if (i < n) { g_degO[i] = 0; g_degI[i] = 0; g_cursor[i] = 0; }
}

__global__ void k_count(const int* __restrict__ src, const int* __restrict__ dst, int E) {
    int e = blockIdx.x * blockDim.x + threadIdx.x;
    if (e < E) {
        atomicAdd(&g_degO[src[e]], 1);
        atomicAdd(&g_degI[dst[e]], 1);
    }
}

// ---------------- scan of g_degI -> g_rowptr (+ fused rsqrt) ----------------
__global__ void k_scan1(int n) {
    __shared__ int sh[512];
    int tid = threadIdx.x;
    int i = blockIdx.x * 512 + tid;
    int v = (i < n) ? g_degI[i] : 0;
    sh[tid] = v;
    if (i < n) {   // fused normalization factors
        g_si[i] = rsqrtf((float)max(v, 1));
        g_so[i] = rsqrtf((float)max(g_degO[i], 1));
    }
    __syncthreads();
    #pragma unroll
    for (int off = 1; off < 512; off <<= 1) {
        int t = (tid >= off) ? sh[tid - off] : 0;
        __syncthreads();
        sh[tid] += t;
        __syncthreads();
    }
    if (i < n) g_rowptr[i] = sh[tid] - v;
    if (tid == 511) g_bsums[blockIdx.x] = sh[511];
}

__global__ void k_scan2(int nb) {
    __shared__ int sh[256];
    int tid = threadIdx.x;
    int v = (tid < nb) ? g_bsums[tid] : 0;
    sh[tid] = v;
    __syncthreads();
    #pragma unroll
    for (int off = 1; off < 256; off <<= 1) {
        int t = (tid >= off) ? sh[tid - off] : 0;
        __syncthreads();
        sh[tid] += t;
        __syncthreads();
    }
    if (tid < nb) g_bsums[tid] = sh[tid] - v;
}

__global__ void k_scan3(int n) {
    int i = blockIdx.x * 512 + threadIdx.x;
    if (i < n) g_rowptr[i] += g_bsums[blockIdx.x];
}

__global__ void k_fill(const int* __restrict__ src, const int* __restrict__ dst, int E) {
    int e = blockIdx.x * blockDim.x + threadIdx.x;
    if (e < E) {
        int d = dst[e];
        int pos = g_rowptr[d] + atomicAdd(&g_cursor[d], 1);
        g_csrc[pos] = src[e];
    }
}

// ---------------- GEMM0: g_bufT = bf16( (X @ W0) * so ) ----------------
__global__ __launch_bounds__(256) void k_gemm0(const float* __restrict__ X,
                                               const float* __restrict__ W0, int N) {
    __shared__ float sX[128][68];
    __shared__ float sW[64][64];
    int tid = threadIdx.x;
    int row0 = blockIdx.x * 128;
    int ty = tid >> 4;   // 0..15 : rows ty*8..+7
    int tx = tid & 15;   // cols tx*4..+3

    float acc[8][4] = {};
    #pragma unroll
    for (int kc = 0; kc < 2; kc++) {
        #pragma unroll
        for (int i = 0; i < 8; i++) {
            int flat = i * 256 + tid;
            int r = flat >> 4, q = flat & 15;
            int gr = row0 + r;
            float4 v = make_float4(0.f, 0.f, 0.f, 0.f);
            if (gr < N) v = *(const float4*)(X + (size_t)gr * 128 + kc * 64 + q * 4);
            *(float4*)&sX[r][q * 4] = v;
        }
        #pragma unroll
        for (int i = 0; i < 4; i++) {
            int flat = i * 256 + tid;
            int k = flat >> 4, q = flat & 15;
            *(float4*)&sW[k][q * 4] = *(const float4*)(W0 + (size_t)(kc * 64 + k) * 64 + q * 4);
        }
        __syncthreads();
        #pragma unroll
        for (int k4 = 0; k4 < 16; k4++) {
            float4 w0 = *(float4*)&sW[k4 * 4 + 0][tx * 4];
            float4 w1 = *(float4*)&sW[k4 * 4 + 1][tx * 4];
            float4 w2 = *(float4*)&sW[k4 * 4 + 2][tx * 4];
            float4 w3 = *(float4*)&sW[k4 * 4 + 3][tx * 4];
            #pragma unroll
            for (int i = 0; i < 8; i++) {
                float4 a = *(float4*)&sX[ty * 8 + i][k4 * 4];
                acc[i][0] += a.x * w0.x + a.y * w1.x + a.z * w2.x + a.w * w3.x;
                acc[i][1] += a.x * w0.y + a.y * w1.y + a.z * w2.y + a.w * w3.y;
                acc[i][2] += a.x * w0.z + a.y * w1.z + a.z * w2.z + a.w * w3.z;
                acc[i][3] += a.x * w0.w + a.y * w1.w + a.z * w2.w + a.w * w3.w;
            }
        }
        __syncthreads();
    }
    #pragma unroll
    for (int i = 0; i < 8; i++) {
        int gr = row0 + ty * 8 + i;
        if (gr < N) {
            float s = g_so[gr];
            float4 o = make_float4(acc[i][0] * s, acc[i][1] * s, acc[i][2] * s, acc[i][3] * s);
            *(uint2*)(g_bufT + (size_t)gr * 64 + tx * 4) = f4_to_bf4(o);
        }
    }
}

// ---------------- CSR pull, 64 feats (bf16), L0 epilogue ----------------
// g_bufA[node] = bf16( relu( (sum g_bufT[src]) * si + b0 ) * so )
__global__ __launch_bounds__(256) void k_pull64_l0(const float* __restrict__ b0, int N) {
    int node = blockIdx.x * 16 + (threadIdx.x >> 4);
    if (node >= N) return;
    int lane = threadIdx.x & 15;
    int start = g_rowptr[node], cnt = g_degI[node];
    float4 acc = make_float4(0.f, 0.f, 0.f, 0.f);
    int j = 0;
    for (; j + 3 < cnt; j += 4) {
        int s0 = __ldg(&g_csrc[start + j]);
        int s1 = __ldg(&g_csrc[start + j + 1]);
        int s2 = __ldg(&g_csrc[start + j + 2]);
        int s3 = __ldg(&g_csrc[start + j + 3]);
        float4 v0 = bf4_to_f4(*(const uint2*)(g_bufT + (size_t)s0 * 64 + lane * 4));
        float4 v1 = bf4_to_f4(*(const uint2*)(g_bufT + (size_t)s1 * 64 + lane * 4));
        float4 v2 = bf4_to_f4(*(const uint2*)(g_bufT + (size_t)s2 * 64 + lane * 4));
        float4 v3 = bf4_to_f4(*(const uint2*)(g_bufT + (size_t)s3 * 64 + lane * 4));
        acc.x += (v0.x + v1.x) + (v2.x + v3.x);
        acc.y += (v0.y + v1.y) + (v2.y + v3.y);
        acc.z += (v0.z + v1.z) + (v2.z + v3.z);
        acc.w += (v0.w + v1.w) + (v2.w + v3.w);
    }
    for (; j < cnt; j++) {
        int s0 = __ldg(&g_csrc[start + j]);
        float4 v0 = bf4_to_f4(*(const uint2*)(g_bufT + (size_t)s0 * 64 + lane * 4));
        acc.x += v0.x; acc.y += v0.y; acc.z += v0.z; acc.w += v0.w;
    }
    float si = g_si[node], so = g_si[node] * 0.f + g_so[node];
    float4 b = *(const float4*)(b0 + lane * 4);
    float4 o;
    o.x = fmaxf(acc.x * si + b.x, 0.f) * so;
    o.y = fmaxf(acc.y * si + b.y, 0.f) * so;
    o.z = fmaxf(acc.z * si + b.z, 0.f) * so;
    o.w = fmaxf(acc.w * si + b.w, 0.f) * so;
    *(uint2*)(g_bufA + (size_t)node * 64 + lane * 4) = f4_to_bf4(o);
}

// ---------------- CSR pull, 64 feats (bf16), L1 aggregation ----------------
// g_agg[node] = (sum g_bufA[src]) * si    (fp32, pre-scaled input to GEMM1)
__global__ __launch_bounds__(256) void k_pull64_l1(int N) {
    int node = blockIdx.x * 16 + (threadIdx.x >> 4);
    if (node >= N) return;
    int lane = threadIdx.x & 15;
    int start = g_rowptr[node], cnt = g_degI[node];
    float4 acc = make_float4(0.f, 0.f, 0.f, 0.f);
    int j = 0;
    for (; j + 3 < cnt; j += 4) {
        int s0 = __ldg(&g_csrc[start + j]);
        int s1 = __ldg(&g_csrc[start + j + 1]);
        int s2 = __ldg(&g_csrc[start + j + 2]);
        int s3 = __ldg(&g_csrc[start + j + 3]);
        float4 v0 = bf4_to_f4(*(const uint2*)(g_bufA + (size_t)s0 * 64 + lane * 4));
        float4 v1 = bf4_to_f4(*(const uint2*)(g_bufA + (size_t)s1 * 64 + lane * 4));
        float4 v2 = bf4_to_f4(*(const uint2*)(g_bufA + (size_t)s2 * 64 + lane * 4));
        float4 v3 = bf4_to_f4(*(const uint2*)(g_bufA + (size_t)s3 * 64 + lane * 4));
        acc.x += (v0.x + v1.x) + (v2.x + v3.x);
        acc.y += (v0.y + v1.y) + (v2.y + v3.y);
        acc.z += (v0.z + v1.z) + (v2.z + v3.z);
        acc.w += (v0.w + v1.w) + (v2.w + v3.w);
    }
    for (; j < cnt; j++) {
        int s0 = __ldg(&g_csrc[start + j]);
        float4 v0 = bf4_to_f4(*(const uint2*)(g_bufA + (size_t)s0 * 64 + lane * 4));
        acc.x += v0.x; acc.y += v0.y; acc.z += v0.z; acc.w += v0.w;
    }
    float si = g_si[node];
    float4 o = make_float4(acc.x * si, acc.y * si, acc.z * si, acc.w * si);
    *(float4*)(g_agg + (size_t)node * 64 + lane * 4) = o;
}

// ---------------- fused L1 GEMM + L2 GEMM ----------------
// in = g_agg (already si-scaled); h1 = relu(in @ W1 + b1); g_bufC = (h1 @ W2) * so
__global__ __launch_bounds__(256) void k_fused12(const float* __restrict__ W1,
                                                 const float* __restrict__ b1,
                                                 const float* __restrict__ W2, int N) {
    __shared__ float sIn[64][68];
    __shared__ float sW1[64][64];
    __shared__ float sW2[64][16];
    int tid = threadIdx.x;
    int row0 = blockIdx.x * 64;
    int ty = tid >> 4, tx = tid & 15;

    #pragma unroll
    for (int i = 0; i < 4; i++) {
        int flat = i * 256 + tid;
        int r = flat >> 4, q = flat & 15;
        int gr = row0 + r;
        float4 v = make_float4(0.f, 0.f, 0.f, 0.f);
        if (gr < N) v = *(const float4*)(g_agg + (size_t)gr * 64 + q * 4);
        *(float4*)&sIn[r][q * 4] = v;
    }
    #pragma unroll
    for (int i = 0; i < 4; i++) {
        int flat = i * 256 + tid;
        int k = flat >> 4, q = flat & 15;
        *(float4*)&sW1[k][q * 4] = *(const float4*)(W1 + (size_t)k * 64 + q * 4);
    }
    {
        int k = tid >> 2, q = tid & 3;
        *(float4*)&sW2[k][q * 4] = *(const float4*)(W2 + (size_t)k * 16 + q * 4);
    }
    __syncthreads();

    float acc[4][4] = {};
    #pragma unroll
    for (int k4 = 0; k4 < 16; k4++) {
        float4 w0 = *(float4*)&sW1[k4 * 4 + 0][tx * 4];
        float4 w1 = *(float4*)&sW1[k4 * 4 + 1][tx * 4];
        float4 w2 = *(float4*)&sW1[k4 * 4 + 2][tx * 4];
        float4 w3 = *(float4*)&sW1[k4 * 4 + 3][tx * 4];
        #pragma unroll
        for (int i = 0; i < 4; i++) {
            float4 a = *(float4*)&sIn[ty * 4 + i][k4 * 4];
            acc[i][0] += a.x * w0.x + a.y * w1.x + a.z * w2.x + a.w * w3.x;
            acc[i][1] += a.x * w0.y + a.y * w1.y + a.z * w2.y + a.w * w3.y;
            acc[i][2] += a.x * w0.z + a.y * w1.z + a.z * w2.z + a.w * w3.z;
            acc[i][3] += a.x * w0.w + a.y * w1.w + a.z * w2.w + a.w * w3.w;
        }
    }
    __syncthreads();
    float4 bb = *(const float4*)(b1 + tx * 4);
    #pragma unroll
    for (int i = 0; i < 4; i++) {
        float4 h;
        h.x = fmaxf(acc[i][0] + bb.x, 0.f);
        h.y = fmaxf(acc[i][1] + bb.y, 0.f);
        h.z = fmaxf(acc[i][2] + bb.z, 0.f);
        h.w = fmaxf(acc[i][3] + bb.w, 0.f);
        *(float4*)&sIn[ty * 4 + i][tx * 4] = h;   // sIn now holds h1
    }
    __syncthreads();

    int row = tid >> 2;
    int cb = (tid & 3) * 4;
    float4 o = make_float4(0.f, 0.f, 0.f, 0.f);
    #pragma unroll 8
    for (int k = 0; k < 64; k++) {
        float a = sIn[row][k];
        float4 w = *(float4*)&sW2[k][cb];
        o.x += a * w.x; o.y += a * w.y; o.z += a * w.z; o.w += a * w.w;
    }
    int gr = row0 + row;
    if (gr < N) {
        float s = g_so[gr];
        o.x *= s; o.y *= s; o.z *= s; o.w *= s;
        *(float4*)(g_bufC + (size_t)gr * 16 + cb) = o;
    }
}

// ---------------- CSR pull, 16 feats (fp32), final ----------------
__global__ __launch_bounds__(256) void k_pull16(const float* __restrict__ b2,
                                                float* __restrict__ out, int N) {
    int node = blockIdx.x * 64 + (threadIdx.x >> 2);
    if (node >= N) return;
    int lane = threadIdx.x & 3;
    int start = g_rowptr[node], cnt = g_degI[node];
    float4 acc = make_float4(0.f, 0.f, 0.f, 0.f);
    int j = 0;
    for (; j + 3 < cnt; j += 4) {
        int s0 = __ldg(&g_csrc[start + j]);
        int s1 = __ldg(&g_csrc[start + j + 1]);
        int s2 = __ldg(&g_csrc[start + j + 2]);
        int s3 = __ldg(&g_csrc[start + j + 3]);
        float4 v0 = *(const float4*)(g_bufC + (size_t)s0 * 16 + lane * 4);
        float4 v1 = *(const float4*)(g_bufC + (size_t)s1 * 16 + lane * 4);
        float4 v2 = *(const float4*)(g_bufC + (size_t)s2 * 16 + lane * 4);
        float4 v3 = *(const float4*)(g_bufC + (size_t)s3 * 16 + lane * 4);
        acc.x += (v0.x + v1.x) + (v2.x + v3.x);
        acc.y += (v0.y + v1.y) + (v2.y + v3.y);
        acc.z += (v0.z + v1.z) + (v2.z + v3.z);
        acc.w += (v0.w + v1.w) + (v2.w + v3.w);
    }
    for (; j < cnt; j++) {
        int s0 = __ldg(&g_csrc[start + j]);
        float4 v0 = *(const float4*)(g_bufC + (size_t)s0 * 16 + lane * 4);
        acc.x += v0.x; acc.y += v0.y; acc.z += v0.z; acc.w += v0.w;
    }
    float si = g_si[node];
    float4 b = *(const float4*)(b2 + lane * 4);
    float4 o = make_float4(acc.x * si + b.x, acc.y * si + b.y,
                           acc.z * si + b.z, acc.w * si + b.w);
    *(float4*)(out + (size_t)node * 16 + lane * 4) = o;
}

extern "C" void kernel_launch(void* const* d_in, const int* in_sizes, int n_in,
                              void* d_out, int out_size) {
    const float* X   = (const float*)d_in[0];
    const int*   src = (const int*)d_in[1];
    const int*   dst = (const int*)d_in[2];
    const float* W0  = (const float*)d_in[3];
    const float* b0  = (const float*)d_in[4];
    const float* W1  = (const float*)d_in[5];
    const float* b1  = (const float*)d_in[6];
    const float* W2  = (const float*)d_in[7];
    const float* b2  = (const float*)d_in[8];
    float* out = (float*)d_out;

    int N = in_sizes[0] / 128;
    int E = in_sizes[1];
    int nb = cdiv(N, 512);

    // degrees + norms + CSR
    k_zero_deg<<<cdiv(N, 256), 256>>>(N);
    k_count<<<cdiv(E, 256), 256>>>(src, dst, E);
    k_scan1<<<nb, 512>>>(N);
    k_scan2<<<1, 256>>>(nb);
    k_scan3<<<nb, 512>>>(N);
    k_fill<<<cdiv(E, 256), 256>>>(src, dst, E);

    // Layer 0
    k_gemm0<<<cdiv(N, 128), 256>>>(X, W0, N);
    k_pull64_l0<<<cdiv(N, 16), 256>>>(b0, N);

    // Layer 1 aggregation + fused GEMMs (L1 + L2)
    k_pull64_l1<<<cdiv(N, 16), 256>>>(N);
    k_fused12<<<cdiv(N, 64), 256>>>(W1, b1, W2, N);

    // Layer 2 aggregation + final
    k_pull16<<<cdiv(N, 64), 256>>>(b2, out, N);
}

// round 4
// speedup vs baseline: 1.6602x; 1.0973x over previous
#include <cuda_runtime.h>
#include <cuda_bf16.h>

#define NMAX 100000
#define EMAX 1600000

// Scratch (allocation-free rule: device globals)
__device__ __nv_bfloat16 g_bufT[NMAX * 64];  // bf16 messages (t0, L0)
__device__ __nv_bfloat16 g_bufA[NMAX * 64];  // bf16 messages (h0*so, L1)
__device__ __nv_bfloat16 g_bufC[NMAX * 16];  // t2 (16-feat messages, bf16)
__device__ float g_so[NMAX];                 // rsqrt(max(deg_out,1))
__device__ float g_si[NMAX];                 // rsqrt(max(deg_in,1))
__device__ int   g_degO[NMAX];
__device__ int   g_degI[NMAX];
__device__ int   g_cursor[NMAX];
__device__ int   g_rowptr[NMAX];             // block-local exclusive scan of degI
__device__ int   g_csrc[EMAX];               // CSR: src ids grouped by dst
__device__ int   g_bsums[512];               // scanned block sums (after k_scan2)

static inline int cdiv(int a, int b) { return (a + b - 1) / b; }

// ---- bf16 pack/unpack helpers ----
__device__ __forceinline__ float4 bf4_to_f4(uint2 r) {
    __nv_bfloat162 lo = *reinterpret_cast<__nv_bfloat162*>(&r.x);
    __nv_bfloat162 hi = *reinterpret_cast<__nv_bfloat162*>(&r.y);
    float2 a = __bfloat1622float2(lo), b = __bfloat1622float2(hi);
    return make_float4(a.x, a.y, b.x, b.y);
}
__device__ __forceinline__ uint2 f4_to_bf4(float4 v) {
    __nv_bfloat162 lo = __float22bfloat162_rn(make_float2(v.x, v.y));
    __nv_bfloat162 hi = __float22bfloat162_rn(make_float2(v.z, v.w));
    uint2 r;
    r.x = *reinterpret_cast<unsigned*>(&lo);
    r.y = *reinterpret_cast<unsigned*>(&hi);
    return r;
}
__device__ __forceinline__ void bf8_acc(uint4 r, float* acc) {
    __nv_bfloat162 h0 = *reinterpret_cast<__nv_bfloat162*>(&r.x);
    __nv_bfloat162 h1 = *reinterpret_cast<__nv_bfloat162*>(&r.y);
    __nv_bfloat162 h2 = *reinterpret_cast<__nv_bfloat162*>(&r.z);
    __nv_bfloat162 h3 = *reinterpret_cast<__nv_bfloat162*>(&r.w);
    float2 f0 = __bfloat1622float2(h0), f1 = __bfloat1622float2(h1);
    float2 f2 = __bfloat1622float2(h2), f3 = __bfloat1622float2(h3);
    acc[0] += f0.x; acc[1] += f0.y; acc[2] += f1.x; acc[3] += f1.y;
    acc[4] += f2.x; acc[5] += f2.y; acc[6] += f3.x; acc[7] += f3.y;
}

// ---------------- degree count (4 edges/thread) ----------------
__global__ void k_count(const int* __restrict__ src, const int* __restrict__ dst, int E) {
    int i = blockIdx.x * blockDim.x + threadIdx.x;
    int base = i * 4;
    if (base + 3 < E) {
        int4 s = *(const int4*)(src + base);
        int4 d = *(const int4*)(dst + base);
        atomicAdd(&g_degO[s.x], 1); atomicAdd(&g_degO[s.y], 1);
        atomicAdd(&g_degO[s.z], 1); atomicAdd(&g_degO[s.w], 1);
        atomicAdd(&g_degI[d.x], 1); atomicAdd(&g_degI[d.y], 1);
        atomicAdd(&g_degI[d.z], 1); atomicAdd(&g_degI[d.w], 1);
    } else {
        for (int e = base; e < E; e++) {
            atomicAdd(&g_degO[src[e]], 1);
            atomicAdd(&g_degI[dst[e]], 1);
        }
    }
}

// ---------------- block-local scan of g_degI (+ fused rsqrt) ----------------
__global__ void k_scan1(int n) {
    __shared__ int sh[512];
    int tid = threadIdx.x;
    int i = blockIdx.x * 512 + tid;
    int v = (i < n) ? g_degI[i] : 0;
    sh[tid] = v;
    if (i < n) {
        g_si[i] = rsqrtf((float)max(v, 1));
        g_so[i] = rsqrtf((float)max(g_degO[i], 1));
    }
    __syncthreads();
    #pragma unroll
    for (int off = 1; off < 512; off <<= 1) {
        int t = (tid >= off) ? sh[tid - off] : 0;
        __syncthreads();
        sh[tid] += t;
        __syncthreads();
    }
    if (i < n) g_rowptr[i] = sh[tid] - v;
    if (tid == 511) g_bsums[blockIdx.x] = sh[511];
}

__global__ void k_scan2(int nb) {
    __shared__ int sh[256];
    int tid = threadIdx.x;
    int v = (tid < nb) ? g_bsums[tid] : 0;
    sh[tid] = v;
    __syncthreads();
    #pragma unroll
    for (int off = 1; off < 256; off <<= 1) {
        int t = (tid >= off) ? sh[tid - off] : 0;
        __syncthreads();
        sh[tid] += t;
        __syncthreads();
    }
    if (tid < nb) g_bsums[tid] = sh[tid] - v;
}

// ---------------- CSR fill (offset folded in) ----------------
__global__ void k_fill(const int* __restrict__ src, const int* __restrict__ dst, int E) {
    int i = blockIdx.x * blockDim.x + threadIdx.x;
    int base = i * 4;
    if (base + 3 < E) {
        int4 s = *(const int4*)(src + base);
        int4 d = *(const int4*)(dst + base);
        int p0 = g_rowptr[d.x] + g_bsums[d.x >> 9] + atomicAdd(&g_cursor[d.x], 1);
        int p1 = g_rowptr[d.y] + g_bsums[d.y >> 9] + atomicAdd(&g_cursor[d.y], 1);
        int p2 = g_rowptr[d.z] + g_bsums[d.z >> 9] + atomicAdd(&g_cursor[d.z], 1);
        int p3 = g_rowptr[d.w] + g_bsums[d.w >> 9] + atomicAdd(&g_cursor[d.w], 1);
        g_csrc[p0] = s.x; g_csrc[p1] = s.y; g_csrc[p2] = s.z; g_csrc[p3] = s.w;
    } else {
        for (int e = base; e < E; e++) {
            int d = dst[e];
            int pos = g_rowptr[d] + g_bsums[d >> 9] + atomicAdd(&g_cursor[d], 1);
            g_csrc[pos] = src[e];
        }
    }
}

// ---------------- GEMM0: g_bufT = bf16( (X @ W0) * so ) ----------------
__global__ __launch_bounds__(256) void k_gemm0(const float* __restrict__ X,
                                               const float* __restrict__ W0, int N) {
    __shared__ float sX[128][68];
    __shared__ float sW[64][64];
    int tid = threadIdx.x;
    int row0 = blockIdx.x * 128;
    int ty = tid >> 4;   // rows ty*8..+7
    int tx = tid & 15;   // cols tx*4..+3

    float acc[8][4] = {};
    #pragma unroll
    for (int kc = 0; kc < 2; kc++) {
        #pragma unroll
        for (int i = 0; i < 8; i++) {
            int flat = i * 256 + tid;
            int r = flat >> 4, q = flat & 15;
            int gr = row0 + r;
            float4 v = make_float4(0.f, 0.f, 0.f, 0.f);
            if (gr < N) v = *(const float4*)(X + (size_t)gr * 128 + kc * 64 + q * 4);
            *(float4*)&sX[r][q * 4] = v;
        }
        #pragma unroll
        for (int i = 0; i < 4; i++) {
            int flat = i * 256 + tid;
            int k = flat >> 4, q = flat & 15;
            *(float4*)&sW[k][q * 4] = *(const float4*)(W0 + (size_t)(kc * 64 + k) * 64 + q * 4);
        }
        __syncthreads();
        #pragma unroll
        for (int k4 = 0; k4 < 16; k4++) {
            float4 w0 = *(float4*)&sW[k4 * 4 + 0][tx * 4];
            float4 w1 = *(float4*)&sW[k4 * 4 + 1][tx * 4];
            float4 w2 = *(float4*)&sW[k4 * 4 + 2][tx * 4];
            float4 w3 = *(float4*)&sW[k4 * 4 + 3][tx * 4];
            #pragma unroll
            for (int i = 0; i < 8; i++) {
                float4 a = *(float4*)&sX[ty * 8 + i][k4 * 4];
                acc[i][0] += a.x * w0.x + a.y * w1.x + a.z * w2.x + a.w * w3.x;
                acc[i][1] += a.x * w0.y + a.y * w1.y + a.z * w2.y + a.w * w3.y;
                acc[i][2] += a.x * w0.z + a.y * w1.z + a.z * w2.z + a.w * w3.z;
                acc[i][3] += a.x * w0.w + a.y * w1.w + a.z * w2.w + a.w * w3.w;
            }
        }
        __syncthreads();
    }
    #pragma unroll
    for (int i = 0; i < 8; i++) {
        int gr = row0 + ty * 8 + i;
        if (gr < N) {
            float s = g_so[gr];
            float4 o = make_float4(acc[i][0] * s, acc[i][1] * s, acc[i][2] * s, acc[i][3] * s);
            *(uint2*)(g_bufT + (size_t)gr * 64 + tx * 4) = f4_to_bf4(o);
        }
    }
}

// ---------------- CSR pull, 64 feats (bf16), L0 epilogue ----------------
// 8 lanes/node, 16B loads.  g_bufA[node] = bf16(relu(sum*si + b0) * so)
__global__ __launch_bounds__(256) void k_pull64_l0(const float* __restrict__ b0, int N) {
    int node = blockIdx.x * 32 + (threadIdx.x >> 3);
    if (node >= N) return;
    int lane = threadIdx.x & 7;
    int start = g_rowptr[node] + g_bsums[node >> 9];
    int cnt = g_degI[node];
    float acc[8] = {};
    int j = 0;
    for (; j + 3 < cnt; j += 4) {
        int s0 = __ldg(&g_csrc[start + j]);
        int s1 = __ldg(&g_csrc[start + j + 1]);
        int s2 = __ldg(&g_csrc[start + j + 2]);
        int s3 = __ldg(&g_csrc[start + j + 3]);
        uint4 r0 = *(const uint4*)(g_bufT + (size_t)s0 * 64 + lane * 8);
        uint4 r1 = *(const uint4*)(g_bufT + (size_t)s1 * 64 + lane * 8);
        uint4 r2 = *(const uint4*)(g_bufT + (size_t)s2 * 64 + lane * 8);
        uint4 r3 = *(const uint4*)(g_bufT + (size_t)s3 * 64 + lane * 8);
        bf8_acc(r0, acc); bf8_acc(r1, acc); bf8_acc(r2, acc); bf8_acc(r3, acc);
    }
    for (; j < cnt; j++) {
        int s0 = __ldg(&g_csrc[start + j]);
        bf8_acc(*(const uint4*)(g_bufT + (size_t)s0 * 64 + lane * 8), acc);
    }
    float si = g_si[node], so = g_so[node];
    float4 ba = *(const float4*)(b0 + lane * 8);
    float4 bb = *(const float4*)(b0 + lane * 8 + 4);
    float4 o0, o1;
    o0.x = fmaxf(acc[0] * si + ba.x, 0.f) * so;
    o0.y = fmaxf(acc[1] * si + ba.y, 0.f) * so;
    o0.z = fmaxf(acc[2] * si + ba.z, 0.f) * so;
    o0.w = fmaxf(acc[3] * si + ba.w, 0.f) * so;
    o1.x = fmaxf(acc[4] * si + bb.x, 0.f) * so;
    o1.y = fmaxf(acc[5] * si + bb.y, 0.f) * so;
    o1.z = fmaxf(acc[6] * si + bb.z, 0.f) * so;
    o1.w = fmaxf(acc[7] * si + bb.w, 0.f) * so;
    uint2 p0 = f4_to_bf4(o0), p1 = f4_to_bf4(o1);
    uint4 pk = make_uint4(p0.x, p0.y, p1.x, p1.y);
    *(uint4*)(g_bufA + (size_t)node * 64 + lane * 8) = pk;
}

// ---------------- fused L1 pull + L1 GEMM + L2 GEMM ----------------
// per 64-node block: sIn = (sum_neighbors g_bufA) * si (pulled in-kernel);
// h1 = relu(sIn @ W1 + b1); g_bufC = bf16((h1 @ W2) * so)
__global__ __launch_bounds__(256) void k_fused_pull12(const float* __restrict__ W1,
                                                      const float* __restrict__ b1,
                                                      const float* __restrict__ W2, int N) {
    __shared__ float sIn[64][68];
    __shared__ float sW1[64][64];
    __shared__ float sW2[64][16];
    int tid = threadIdx.x;
    int row0 = blockIdx.x * 64;

    // weight loads (independent of pull)
    #pragma unroll
    for (int i = 0; i < 4; i++) {
        int flat = i * 256 + tid;
        int k = flat >> 4, q = flat & 15;
        *(float4*)&sW1[k][q * 4] = *(const float4*)(W1 + (size_t)k * 64 + q * 4);
    }
    {
        int k = tid >> 2, q = tid & 3;
        *(float4*)&sW2[k][q * 4] = *(const float4*)(W2 + (size_t)k * 16 + q * 4);
    }

    // pull phase: 8 lanes/node, 32 nodes per pass, 2 passes
    int lane = tid & 7;
    #pragma unroll
    for (int pass = 0; pass < 2; pass++) {
        int local = pass * 32 + (tid >> 3);
        int node = row0 + local;
        float acc[8] = {};
        if (node < N) {
            int start = g_rowptr[node] + g_bsums[node >> 9];
            int cnt = g_degI[node];
            int j = 0;
            for (; j + 3 < cnt; j += 4) {
                int s0 = __ldg(&g_csrc[start + j]);
                int s1 = __ldg(&g_csrc[start + j + 1]);
                int s2 = __ldg(&g_csrc[start + j + 2]);
                int s3 = __ldg(&g_csrc[start + j + 3]);
                uint4 r0 = *(const uint4*)(g_bufA + (size_t)s0 * 64 + lane * 8);
                uint4 r1 = *(const uint4*)(g_bufA + (size_t)s1 * 64 + lane * 8);
                uint4 r2 = *(const uint4*)(g_bufA + (size_t)s2 * 64 + lane * 8);
                uint4 r3 = *(const uint4*)(g_bufA + (size_t)s3 * 64 + lane * 8);
                bf8_acc(r0, acc); bf8_acc(r1, acc); bf8_acc(r2, acc); bf8_acc(r3, acc);
            }
            for (; j < cnt; j++) {
                int s0 = __ldg(&g_csrc[start + j]);
                bf8_acc(*(const uint4*)(g_bufA + (size_t)s0 * 64 + lane * 8), acc);
            }
            float si = g_si[node];
            #pragma unroll
            for (int t = 0; t < 8; t++) acc[t] *= si;
        }
        *(float4*)&sIn[local][lane * 8]     = make_float4(acc[0], acc[1], acc[2], acc[3]);
        *(float4*)&sIn[local][lane * 8 + 4] = make_float4(acc[4], acc[5], acc[6], acc[7]);
    }
    __syncthreads();

    // phase 1: h1 = relu(sIn @ W1 + b1)
    int ty = tid >> 4, tx = tid & 15;
    float acc[4][4] = {};
    #pragma unroll
    for (int k4 = 0; k4 < 16; k4++) {
        float4 w0 = *(float4*)&sW1[k4 * 4 + 0][tx * 4];
        float4 w1 = *(float4*)&sW1[k4 * 4 + 1][tx * 4];
        float4 w2 = *(float4*)&sW1[k4 * 4 + 2][tx * 4];
        float4 w3 = *(float4*)&sW1[k4 * 4 + 3][tx * 4];
        #pragma unroll
        for (int i = 0; i < 4; i++) {
            float4 a = *(float4*)&sIn[ty * 4 + i][k4 * 4];
            acc[i][0] += a.x * w0.x + a.y * w1.x + a.z * w2.x + a.w * w3.x;
            acc[i][1] += a.x * w0.y + a.y * w1.y + a.z * w2.y + a.w * w3.y;
            acc[i][2] += a.x * w0.z + a.y * w1.z + a.z * w2.z + a.w * w3.z;
            acc[i][3] += a.x * w0.w + a.y * w1.w + a.z * w2.w + a.w * w3.w;
        }
    }
    __syncthreads();
    float4 bb = *(const float4*)(b1 + tx * 4);
    #pragma unroll
    for (int i = 0; i < 4; i++) {
        float4 h;
        h.x = fmaxf(acc[i][0] + bb.x, 0.f);
        h.y = fmaxf(acc[i][1] + bb.y, 0.f);
        h.z = fmaxf(acc[i][2] + bb.z, 0.f);
        h.w = fmaxf(acc[i][3] + bb.w, 0.f);
        *(float4*)&sIn[ty * 4 + i][tx * 4] = h;   // sIn now holds h1
    }
    __syncthreads();

    // phase 2: g_bufC = bf16((h1 @ W2) * so)
    int row = tid >> 2;
    int cb = (tid & 3) * 4;
    float4 o = make_float4(0.f, 0.f, 0.f, 0.f);
    #pragma unroll 8
    for (int k = 0; k < 64; k++) {
        float a = sIn[row][k];
        float4 w = *(float4*)&sW2[k][cb];
        o.x += a * w.x; o.y += a * w.y; o.z += a * w.z; o.w += a * w.w;
    }
    int gr = row0 + row;
    if (gr < N) {
        float s = g_so[gr];
        o.x *= s; o.y *= s; o.z *= s; o.w *= s;
        *(uint2*)(g_bufC + (size_t)gr * 16 + cb) = f4_to_bf4(o);
    }
}

// ---------------- CSR pull, 16 feats (bf16), final ----------------
__global__ __launch_bounds__(256) void k_pull16(const float* __restrict__ b2,
                                                float* __restrict__ out, int N) {
    int node = blockIdx.x * 64 + (threadIdx.x >> 2);
    if (node >= N) return;
    int lane = threadIdx.x & 3;
    int start = g_rowptr[node] + g_bsums[node >> 9];
    int cnt = g_degI[node];
    float4 acc = make_float4(0.f, 0.f, 0.f, 0.f);
    int j = 0;
    for (; j + 3 < cnt; j += 4) {
        int s0 = __ldg(&g_csrc[start + j]);
        int s1 = __ldg(&g_csrc[start + j + 1]);
        int s2 = __ldg(&g_csrc[start + j + 2]);
        int s3 = __ldg(&g_csrc[start + j + 3]);
        float4 v0 = bf4_to_f4(*(const uint2*)(g_bufC + (size_t)s0 * 16 + lane * 4));
        float4 v1 = bf4_to_f4(*(const uint2*)(g_bufC + (size_t)s1 * 16 + lane * 4));
        float4 v2 = bf4_to_f4(*(const uint2*)(g_bufC + (size_t)s2 * 16 + lane * 4));
        float4 v3 = bf4_to_f4(*(const uint2*)(g_bufC + (size_t)s3 * 16 + lane * 4));
        acc.x += (v0.x + v1.x) + (v2.x + v3.x);
        acc.y += (v0.y + v1.y) + (v2.y + v3.y);
        acc.z += (v0.z + v1.z) + (v2.z + v3.z);
        acc.w += (v0.w + v1.w) + (v2.w + v3.w);
    }
    for (; j < cnt; j++) {
        int s0 = __ldg(&g_csrc[start + j]);
        float4 v0 = bf4_to_f4(*(const uint2*)(g_bufC + (size_t)s0 * 16 + lane * 4));
        acc.x += v0.x; acc.y += v0.y; acc.z += v0.z; acc.w += v0.w;
    }
    float si = g_si[node];
    float4 b = *(const float4*)(b2 + lane * 4);
    float4 o = make_float4(acc.x * si + b.x, acc.y * si + b.y,
                           acc.z * si + b.z, acc.w * si + b.w);
    *(float4*)(out + (size_t)node * 16 + lane * 4) = o;
}

extern "C" void kernel_launch(void* const* d_in, const int* in_sizes, int n_in,
                              void* d_out, int out_size) {
    const float* X   = (const float*)d_in[0];
    const int*   src = (const int*)d_in[1];
    const int*   dst = (const int*)d_in[2];
    const float* W0  = (const float*)d_in[3];
    const float* b0  = (const float*)d_in[4];
    const float* W1  = (const float*)d_in[5];
    const float* b1  = (const float*)d_in[6];
    const float* W2  = (const float*)d_in[7];
    const float* b2  = (const float*)d_in[8];
    float* out = (float*)d_out;

    int N = in_sizes[0] / 128;
    int E = in_sizes[1];
    int nb = cdiv(N, 512);

    // side stream + events, created once (resource init only; work is identical every call)
    static cudaStream_t s_side = nullptr;
    static cudaEvent_t ev_fork = nullptr, ev_join = nullptr;
    static int res_init = 0;
    if (!res_init) {
        res_init = 1;
        if (cudaStreamCreateWithFlags(&s_side, cudaStreamNonBlocking) != cudaSuccess) s_side = nullptr;
        if (s_side) {
            if (cudaEventCreateWithFlags(&ev_fork, cudaEventDisableTiming) != cudaSuccess ||
                cudaEventCreateWithFlags(&ev_join, cudaEventDisableTiming) != cudaSuccess) {
                s_side = nullptr;
            }
        }
    }

    // zero deg/cursor via memset nodes
    void *pO = nullptr, *pI = nullptr, *pC = nullptr;
    cudaGetSymbolAddress(&pO, g_degO);
    cudaGetSymbolAddress(&pI, g_degI);
    cudaGetSymbolAddress(&pC, g_cursor);
    cudaMemsetAsync(pO, 0, (size_t)N * sizeof(int), 0);
    cudaMemsetAsync(pI, 0, (size_t)N * sizeof(int), 0);
    cudaMemsetAsync(pC, 0, (size_t)N * sizeof(int), 0);

    k_count<<<cdiv(E, 1024), 256>>>(src, dst, E);
    k_scan1<<<nb, 512>>>(N);

    // fork: gemm0 only needs g_so (written by k_scan1)
    if (s_side) {
        cudaEventRecord(ev_fork, 0);
        cudaStreamWaitEvent(s_side, ev_fork, 0);
        k_gemm0<<<cdiv(N, 128), 256, 0, s_side>>>(X, W0, N);
        cudaEventRecord(ev_join, s_side);
    }

    k_scan2<<<1, 256>>>(nb);
    k_fill<<<cdiv(E, 1024), 256>>>(src, dst, E);

    if (s_side) cudaStreamWaitEvent(0, ev_join, 0);
    else        k_gemm0<<<cdiv(N, 128), 256>>>(X, W0, N);

    // Layer 0 aggregation + epilogue
    k_pull64_l0<<<cdiv(N, 32), 256>>>(b0, N);

    // Layer 1 aggregation fused with L1+L2 GEMMs
    k_fused_pull12<<<cdiv(N, 64), 256>>>(W1, b1, W2, N);

    // Layer 2 aggregation + final
    k_pull16<<<cdiv(N, 64), 256>>>(b2, out, N);
}